// round 14
// baseline (speedup 1.0000x reference)
#include <cuda_runtime.h>
#include <cuda_bf16.h>

// ES-RNN (Holt-Winters) forward scan, warp-specialized producer/consumer,
// fully vectorized smem path (LDS.128/STS.128, conflict-free stride 20).
// Block = 64 threads: warp0 computes 32 series (smem-only), warp1 does all
// global I/O (prefetch y, flush outputs), double-buffered.
// Output (flattened): levels[N,512] | seasonalities[N,536] | logd[N,511], f32.

#define NTIME 512
#define SEASW 536
#define LOGW  511
#define STR   20      // floats per smem row: 16B-aligned rows AND (lane*20+4c)%32
                      // is a perfect bank permutation per 8-lane phase -> no conflicts

// ---------------- IO-warp helpers (32 lanes) ----------------

__device__ __forceinline__ void io_load(const float* __restrict__ y, int sbase,
                                        int n, int tile, int lane, float4 (&pf)[4]) {
#pragma unroll
    for (int k = 0; k < 4; ++k) {
        int l = lane + 32 * k;          // 0..127 -> 128 float4 = 32 rows x 16 cols
        int row = l >> 2, c4 = l & 3;
        int sr = sbase + row;
        pf[k] = (sr < n) ? *(const float4*)(y + (size_t)sr * NTIME + tile * 16 + 4 * c4)
                         : make_float4(1.f, 1.f, 1.f, 1.f);
    }
}

__device__ __forceinline__ void io_sts(float* buf, int lane, const float4 (&pf)[4]) {
#pragma unroll
    for (int k = 0; k < 4; ++k) {
        int l = lane + 32 * k;
        int row = l >> 2, c4 = l & 3;
        *(float4*)(buf + row * STR + 4 * c4) = pf[k];   // STS.128
    }
}

__device__ __forceinline__ void io_flush_f4(const float* buf, float* g, int rowstride,
                                            int coloff, int sbase, int n, int lane) {
#pragma unroll
    for (int k = 0; k < 4; ++k) {
        int l = lane + 32 * k;
        int row = l >> 2, c4 = l & 3;
        float4 v = *(const float4*)(buf + row * STR + 4 * c4);  // LDS.128
        int sr = sbase + row;
        if (sr < n) *(float4*)(g + (size_t)sr * rowstride + coloff + 4 * c4) = v;
    }
}

__device__ __forceinline__ void io_flush_logd(const float* buf, float* g, int tile,
                                              int sbase, int n, int lane) {
#pragma unroll
    for (int k = 0; k < 4; ++k) {
        int l = lane + 32 * k;
        int row = l >> 2, c4 = l & 3;
        float4 v = *(const float4*)(buf + row * STR + 4 * c4);  // LDS.128
        int sr = sbase + row;
        if (sr < n) {
            float* grow = g + (size_t)sr * LOGW;
            const float vv[4] = {v.x, v.y, v.z, v.w};
#pragma unroll
            for (int jj = 0; jj < 4; ++jj) {
                int gcol = tile * 16 + 4 * c4 + jj - 1;  // logd[t] at t-1; t=0 skipped
                if (gcol >= 0) grow[gcol] = vv[jj];
            }
        }
    }
}

// ---------------- compute warp: 16 steps, PHASE = (16*tile)%24 ----------------

template<int PHASE, bool FIRST>
__device__ __forceinline__ void compute_tile(
    const float* yrow, float* lrow, float* srow, float* drow,
    float (&S)[24], float& lev, float& loglev, float a)
{
    float yv[16], q[16];
#pragma unroll
    for (int k = 0; k < 4; ++k) {                 // 4x LDS.128
        float4 v = ((const float4*)yrow)[k];
        yv[4 * k + 0] = v.x; yv[4 * k + 1] = v.y;
        yv[4 * k + 2] = v.z; yv[4 * k + 3] = v.w;
    }
    // positions within a tile are distinct (16 < 24) -> all divisions use
    // pre-tile seasonal state: 16 independent MUFU RCPs, fully pipelined.
#pragma unroll
    for (int j = 0; j < 16; ++j) q[j] = __fdividef(yv[j], S[(PHASE + j) % 24]);

#pragma unroll
    for (int k = 0; k < 4; ++k) {
        float lo[4], so[4], dd[4];
#pragma unroll
        for (int jj = 0; jj < 4; ++jj) {
            const int j = 4 * k + jj;
            if (FIRST && j == 0) {
                lev = q[0];                  // lev0 = y0 / init_seas0
                loglev = __logf(lev);
                lo[0] = lev;
                so[0] = S[0];                // seasonalities[24] = init_seas[:,0]
                dd[0] = 0.0f;                // slot skipped by flush
            } else {
                const int pos = (PHASE + j) % 24;
                float seas = S[pos];
                float nl  = fmaf(a, q[j] - lev, lev);
                float ns  = fmaf(a, __fdividef(yv[j], nl) - seas, seas);
                float nlg = __logf(nl);
                dd[jj] = nlg - loglev;
                lo[jj] = nl;
                so[jj] = ns;
                lev = nl; loglev = nlg; S[pos] = ns;
            }
        }
        ((float4*)lrow)[k] = make_float4(lo[0], lo[1], lo[2], lo[3]);  // STS.128
        ((float4*)srow)[k] = make_float4(so[0], so[1], so[2], so[3]);
        ((float4*)drow)[k] = make_float4(dd[0], dd[1], dd[2], dd[3]);
    }
}

__global__ __launch_bounds__(64)
void ES_51994874085958_kernel(
    const float* __restrict__ y,
    const int*   __restrict__ idxs,
    const float* __restrict__ lev_sms_p,
    const float* __restrict__ init_seas_p,
    float*       __restrict__ out,
    int n_series)
{
    __shared__ float shY[2][32 * STR];
    __shared__ float shLev[2][32 * STR];
    __shared__ float shSeas[2][32 * STR];
    __shared__ float shLogd[2][32 * STR];
    __shared__ float shInit[32 * 25];    // 32 series x 24 init seasonals (stride 25)

    const int tid  = threadIdx.x;
    const int lane = tid & 31;
    const bool is_compute = (tid < 32);
    const int sbase = blockIdx.x * 32;

    float* out_lev  = out;
    float* out_seas = out + (size_t)n_series * NTIME;
    float* out_logd = out + (size_t)n_series * (NTIME + SEASW);

    float a = 0.5f, lev = 1.0f, loglev = 0.0f;
    float S[24];
    float4 pf[4];

    if (is_compute) {
        int s = sbase + lane;
        if (s < n_series) {
            int idx = idxs[s];
            // reference uses lev_sms for BOTH smoothing coefficients
            a = 1.0f / (1.0f + __expf(-lev_sms_p[idx]));
            const float4* is4 = (const float4*)(init_seas_p + (size_t)idx * 24);
#pragma unroll
            for (int k = 0; k < 6; ++k) {
                float4 v = is4[k];
                S[4 * k + 0] = __expf(v.x);
                S[4 * k + 1] = __expf(v.y);
                S[4 * k + 2] = __expf(v.z);
                S[4 * k + 3] = __expf(v.w);
            }
        } else {
#pragma unroll
            for (int k = 0; k < 24; ++k) S[k] = 1.0f;
        }
#pragma unroll
        for (int k = 0; k < 24; ++k) shInit[lane * 25 + k] = S[k];
    } else {
        io_load(y, sbase, n_series, 0, lane, pf);
        io_sts(shY[0], lane, pf);
    }
    __syncthreads();

    // Tile i: compute reads shY[i&1], writes out-bufs[i&1].
    // IO: prefetch y tile i+1 into shY[(i+1)&1]; flush out-bufs[(i-1)&1] of tile i-1.
#define ITER(I, PHASE, FIRST, B) do {                                              \
        if (is_compute) {                                                          \
            compute_tile<PHASE, FIRST>(shY[B] + lane * STR, shLev[B] + lane * STR, \
                                       shSeas[B] + lane * STR, shLogd[B] + lane * STR, \
                                       S, lev, loglev, a);                         \
        } else {                                                                   \
            if ((I) + 1 < 32) io_load(y, sbase, n_series, (I) + 1, lane, pf);      \
            if (FIRST) {                                                           \
                /* seasonalities[:, 0:24] = exp(init_seas), coalesced */           \
                for (int r = 0; r < 32; ++r) {                                     \
                    int sr = sbase + r;                                            \
                    if (lane < 24 && sr < n_series)                                \
                        out_seas[(size_t)sr * SEASW + lane] = shInit[r * 25 + lane];\
                }                                                                  \
            } else {                                                               \
                io_flush_f4(shLev[1 - (B)],  out_lev,  NTIME, ((I) - 1) * 16,      \
                            sbase, n_series, lane);                                \
                io_flush_f4(shSeas[1 - (B)], out_seas, SEASW, 24 + ((I) - 1) * 16, \
                            sbase, n_series, lane);                                \
                io_flush_logd(shLogd[1 - (B)], out_logd, (I) - 1,                  \
                              sbase, n_series, lane);                              \
            }                                                                      \
            if ((I) + 1 < 32) io_sts(shY[((I) + 1) & 1], lane, pf);                \
        }                                                                          \
        __syncthreads();                                                           \
    } while (0)

    ITER(0, 0, true, 0);

    int i = 1;
#pragma unroll 1
    for (int g = 0; g < 5; ++g) {       // tiles 1..30, period-6 (phase x parity)
        ITER(i, 16, false, 1); ++i;
        ITER(i,  8, false, 0); ++i;
        ITER(i,  0, false, 1); ++i;
        ITER(i, 16, false, 0); ++i;
        ITER(i,  8, false, 1); ++i;
        ITER(i,  0, false, 0); ++i;
    }

    ITER(31, 16, false, 1);

    // drain: flush tile 31 (bufs parity 1)
    if (!is_compute) {
        io_flush_f4(shLev[1],  out_lev,  NTIME, 31 * 16,      sbase, n_series, lane);
        io_flush_f4(shSeas[1], out_seas, SEASW, 24 + 31 * 16, sbase, n_series, lane);
        io_flush_logd(shLogd[1], out_logd, 31, sbase, n_series, lane);
    }
#undef ITER
}

extern "C" void kernel_launch(void* const* d_in, const int* in_sizes, int n_in,
                              void* d_out, int out_size)
{
    const float* y         = (const float*)d_in[0];
    const int*   idxs      = (const int*)d_in[1];
    const float* lev_sms   = (const float*)d_in[2];
    // d_in[3] = seas_sms: unused by the reference (it re-uses lev_sms).
    const float* init_seas = (const float*)d_in[4];

    int n_series = in_sizes[0] / NTIME;
    int blocks   = (n_series + 31) / 32;

    ES_51994874085958_kernel<<<blocks, 64>>>(
        y, idxs, lev_sms, init_seas, (float*)d_out, n_series);
}

// round 16
// speedup vs baseline: 1.2749x; 1.2749x over previous
#include <cuda_runtime.h>
#include <cuda_bf16.h>

// ES-RNN (Holt-Winters) forward scan.
// 256-thread blocks: warps 0-3 = compute (one 32-series group each, on SMSP 0-3
// so MUFU work spreads across all 4 sub-partitions), warps 4-7 = IO (prefetch y,
// flush outputs for the matching group), double-buffered. Scalar smem staging
// with stride 17 (proven best in R9).
// Output (flattened): levels[N,512] | seasonalities[N,536] | logd[N,511], f32.

#define NTIME 512
#define SEASW 536
#define LOGW  511
#define STR   17              // odd stride -> conflict-free scalar smem access
#define GROUPS 4
#define BUFSZ (32 * STR)      // 544 floats per buffer
#define GRPSZ (8 * BUFSZ)     // Y0,Y1,L0,L1,S0,S1,D0,D1
#define INITSZ (32 * 25)      // init-seas staging per group

// ---------------- IO-warp helpers (32 lanes) ----------------

__device__ __forceinline__ void io_load(const float* __restrict__ y, int sbase,
                                        int n, int tile, int lane, float4 (&pf)[4]) {
#pragma unroll
    for (int k = 0; k < 4; ++k) {
        int l = lane + 32 * k;          // 0..127 -> 128 float4 = 32 rows x 16 cols
        int row = l >> 2, c4 = l & 3;
        int sr = sbase + row;
        pf[k] = (sr < n) ? *(const float4*)(y + (size_t)sr * NTIME + tile * 16 + 4 * c4)
                         : make_float4(1.f, 1.f, 1.f, 1.f);
    }
}

__device__ __forceinline__ void io_sts(float* buf, int lane, const float4 (&pf)[4]) {
#pragma unroll
    for (int k = 0; k < 4; ++k) {
        int l = lane + 32 * k;
        int row = l >> 2, c4 = l & 3;
        float* p = buf + row * STR + 4 * c4;
        p[0] = pf[k].x; p[1] = pf[k].y; p[2] = pf[k].z; p[3] = pf[k].w;
    }
}

__device__ __forceinline__ void io_flush_f4(const float* buf, float* g, int rowstride,
                                            int coloff, int sbase, int n, int lane) {
#pragma unroll
    for (int k = 0; k < 4; ++k) {
        int l = lane + 32 * k;
        int row = l >> 2, c4 = l & 3;
        const float* p = buf + row * STR + 4 * c4;
        float4 v = make_float4(p[0], p[1], p[2], p[3]);
        int sr = sbase + row;
        if (sr < n) *(float4*)(g + (size_t)sr * rowstride + coloff + 4 * c4) = v;
    }
}

__device__ __forceinline__ void io_flush_logd(const float* buf, float* g, int tile,
                                              int sbase, int n, int lane) {
#pragma unroll
    for (int k = 0; k < 16; ++k) {
        int l = lane + 32 * k;          // 512 values = 32 rows x 16 cols
        int row = l >> 4, col = l & 15;
        int gcol = tile * 16 + col - 1; // logd[t] lives at t-1; t=0 skipped
        int sr = sbase + row;
        if (gcol >= 0 && sr < n) g[(size_t)sr * LOGW + gcol] = buf[row * STR + col];
    }
}

// ---------------- compute warp: 16 steps, PHASE = (16*tile)%24 ----------------

template<int PHASE, bool FIRST>
__device__ __forceinline__ void compute_tile(
    const float* yrow, float* lrow, float* srow, float* drow,
    float (&S)[24], float& lev, float& loglev, float a)
{
    float yv[16], q[16];
#pragma unroll
    for (int j = 0; j < 16; ++j) yv[j] = yrow[j];
    // positions within a tile are distinct (16 < 24) -> all divisions use
    // pre-tile seasonal state: 16 independent MUFU RCPs, fully pipelined.
#pragma unroll
    for (int j = 0; j < 16; ++j) q[j] = __fdividef(yv[j], S[(PHASE + j) % 24]);
#pragma unroll
    for (int j = 0; j < 16; ++j) {
        if (FIRST && j == 0) {
            lev = q[0];                  // lev0 = y0 / init_seas0
            loglev = __logf(lev);
            lrow[0] = lev;
            srow[0] = S[0];              // seasonalities[24] = init_seas[:,0]
        } else {
            const int pos = (PHASE + j) % 24;
            float seas = S[pos];
            float nl  = fmaf(a, q[j] - lev, lev);
            float ns  = fmaf(a, __fdividef(yv[j], nl) - seas, seas);
            float nlg = __logf(nl);
            drow[j] = nlg - loglev;
            lrow[j] = nl;
            srow[j] = ns;
            lev = nl; loglev = nlg; S[pos] = ns;
        }
    }
}

__global__ __launch_bounds__(256)
void ES_51994874085958_kernel(
    const float* __restrict__ y,
    const int*   __restrict__ idxs,
    const float* __restrict__ lev_sms_p,
    const float* __restrict__ init_seas_p,
    float*       __restrict__ out,
    int n_series)
{
    extern __shared__ float dsm[];

    const int tid  = threadIdx.x;
    const int wid  = tid >> 5;
    const int lane = tid & 31;
    const bool is_compute = (wid < GROUPS);            // warps 0-3 -> SMSP 0-3
    const int group = is_compute ? wid : (wid - GROUPS);
    const int sbase = blockIdx.x * (32 * GROUPS) + group * 32;

    // per-group smem partition: Y0,Y1,L0,L1,S0,S1,D0,D1 then shInit region
    float* gbase  = dsm + group * GRPSZ;
    float* bufY[2]   = { gbase + 0 * BUFSZ, gbase + 1 * BUFSZ };
    float* bufL[2]   = { gbase + 2 * BUFSZ, gbase + 3 * BUFSZ };
    float* bufS[2]   = { gbase + 4 * BUFSZ, gbase + 5 * BUFSZ };
    float* bufD[2]   = { gbase + 6 * BUFSZ, gbase + 7 * BUFSZ };
    float* shInit    = dsm + GROUPS * GRPSZ + group * INITSZ;

    float* out_lev  = out;
    float* out_seas = out + (size_t)n_series * NTIME;
    float* out_logd = out + (size_t)n_series * (NTIME + SEASW);

    float a = 0.5f, lev = 1.0f, loglev = 0.0f;
    float S[24];
    float4 pf[4];

    if (is_compute) {
        int s = sbase + lane;
        if (s < n_series) {
            int idx = idxs[s];
            // reference uses lev_sms for BOTH smoothing coefficients
            a = 1.0f / (1.0f + __expf(-lev_sms_p[idx]));
            const float4* is4 = (const float4*)(init_seas_p + (size_t)idx * 24);
#pragma unroll
            for (int k = 0; k < 6; ++k) {
                float4 v = is4[k];
                S[4 * k + 0] = __expf(v.x);
                S[4 * k + 1] = __expf(v.y);
                S[4 * k + 2] = __expf(v.z);
                S[4 * k + 3] = __expf(v.w);
            }
        } else {
#pragma unroll
            for (int k = 0; k < 24; ++k) S[k] = 1.0f;
        }
#pragma unroll
        for (int k = 0; k < 24; ++k) shInit[lane * 25 + k] = S[k];
    } else {
        io_load(y, sbase, n_series, 0, lane, pf);
        io_sts(bufY[0], lane, pf);
    }
    __syncthreads();

    // Tile i: compute reads bufY[i&1], writes out-bufs[i&1].
    // IO: prefetch y tile i+1 into bufY[(i+1)&1]; flush out-bufs[(i-1)&1].
#define ITER(I, PHASE, FIRST, B) do {                                              \
        if (is_compute) {                                                          \
            compute_tile<PHASE, FIRST>(bufY[B] + lane * STR, bufL[B] + lane * STR, \
                                       bufS[B] + lane * STR, bufD[B] + lane * STR, \
                                       S, lev, loglev, a);                         \
        } else {                                                                   \
            if ((I) + 1 < 32) io_load(y, sbase, n_series, (I) + 1, lane, pf);      \
            if (FIRST) {                                                           \
                /* seasonalities[:, 0:24] = exp(init_seas), coalesced */           \
                for (int r = 0; r < 32; ++r) {                                     \
                    int sr = sbase + r;                                            \
                    if (lane < 24 && sr < n_series)                                \
                        out_seas[(size_t)sr * SEASW + lane] = shInit[r * 25 + lane];\
                }                                                                  \
            } else {                                                               \
                io_flush_f4(bufL[1 - (B)],  out_lev,  NTIME, ((I) - 1) * 16,       \
                            sbase, n_series, lane);                                \
                io_flush_f4(bufS[1 - (B)], out_seas, SEASW, 24 + ((I) - 1) * 16,   \
                            sbase, n_series, lane);                                \
                io_flush_logd(bufD[1 - (B)], out_logd, (I) - 1,                    \
                              sbase, n_series, lane);                              \
            }                                                                      \
            if ((I) + 1 < 32) io_sts(bufY[((I) + 1) & 1], lane, pf);               \
        }                                                                          \
        __syncthreads();                                                           \
    } while (0)

    ITER(0, 0, true, 0);

    int i = 1;
#pragma unroll 1
    for (int g = 0; g < 5; ++g) {       // tiles 1..30, period-6 (phase x parity)
        ITER(i, 16, false, 1); ++i;
        ITER(i,  8, false, 0); ++i;
        ITER(i,  0, false, 1); ++i;
        ITER(i, 16, false, 0); ++i;
        ITER(i,  8, false, 1); ++i;
        ITER(i,  0, false, 0); ++i;
    }

    ITER(31, 16, false, 1);

    // drain: flush tile 31 (bufs parity 1)
    if (!is_compute) {
        io_flush_f4(bufL[1],  out_lev,  NTIME, 31 * 16,      sbase, n_series, lane);
        io_flush_f4(bufS[1], out_seas, SEASW, 24 + 31 * 16, sbase, n_series, lane);
        io_flush_logd(bufD[1], out_logd, 31, sbase, n_series, lane);
    }
#undef ITER
}

extern "C" void kernel_launch(void* const* d_in, const int* in_sizes, int n_in,
                              void* d_out, int out_size)
{
    const float* y         = (const float*)d_in[0];
    const int*   idxs      = (const int*)d_in[1];
    const float* lev_sms   = (const float*)d_in[2];
    // d_in[3] = seas_sms: unused by the reference (it re-uses lev_sms).
    const float* init_seas = (const float*)d_in[4];

    int n_series = in_sizes[0] / NTIME;
    int blocks   = (n_series + 32 * GROUPS - 1) / (32 * GROUPS);

    const int smem_bytes = (GROUPS * GRPSZ + GROUPS * INITSZ) * (int)sizeof(float);
    // idempotent; driver-state change, not a captured stream op
    cudaFuncSetAttribute(ES_51994874085958_kernel,
                         cudaFuncAttributeMaxDynamicSharedMemorySize, smem_bytes);

    ES_51994874085958_kernel<<<blocks, 256, smem_bytes>>>(
        y, idxs, lev_sms, init_seas, (float*)d_out, n_series);
}